// round 7
// baseline (speedup 1.0000x reference)
#include <cuda_runtime.h>
#include <math.h>

// Problem constants
#define BB 128
#define SS 256
#define HH 1024
#define EE 512
#define ENVD 896
#define VV 10000
#define INSZ 3456          // E + H + H + ENV = 512+1024+1024+896
#define MATT (SS*BB)       // 32768
#define G4H 4096

// Accurate fp32 tanh immune to --use_fast_math's tanh.approx.
__device__ __forceinline__ float tanh_acc(float x) {
    float ax = fabsf(x);
    float e  = __expf(2.0f * ax);
    float t  = 1.0f - 2.0f / (e + 1.0f);
    return copysignf(t, x);
}

// ---------------- scratch (device globals; no allocation) ----------------
// RULE: these symbols are ONLY referenced inside device code. Passing them as
// kernel arguments from host code passes the HOST shadow address (UB), which
// on GB300 is silently dereferenceable via ATS — that was the bug.
__device__ float g_x[BB*INSZ];          // LSTM input concat [B,3456]
__device__ float g_hp[BB*HH];           // h@W_hp + b_hp + b_ep
__device__ float g_hc[BB*HH];           // h@W_hc + b_hc + b_ec
__device__ float g_U[MATT*HH];          // enc@W_e scratch [32768,1024] (reused)
__device__ float g_sP[MATT];            // scores prev, layout [s*B+b]
__device__ float g_sC[MATT];            // scores cur
__device__ float g_wP[MATT];            // softmax weights, layout [s*B+b]
__device__ float g_wC[MATT];
__device__ float g_gpart[5*BB*G4H];     // gates K-split partials
__device__ float g_gates[BB*G4H];
__device__ float g_opart[2*BB*VV];      // output GEMM K-split partials
__device__ float g_h1[BB*HH];
__device__ float g_c1[BB*HH];

// ---------------- shared 128x128x8 fp32 GEMM core ----------------
__device__ __forceinline__ void gemm_core(
    const float* __restrict__ A, int lda,
    const float* __restrict__ Wn, int ldw,
    int k0, int k1, int nvalid,
    float (&acc)[8][8], float* As, float* Bs)
{
    const int t  = threadIdx.x;
    const int tx = t & 15, ty = t >> 4;
    const int ar = t >> 1;            // A row 0..127
    const int ac = (t & 1) << 2;      // A k-subcol 0 or 4
    const int bk = t >> 5;            // B k-row 0..7
    const int bc = (t & 31) << 2;     // B n-subcol 0..124

    for (int kt = k0; kt < k1; kt += 8) {
        float4 a4 = *(const float4*)(A + (size_t)ar*lda + kt + ac);
        As[(ac+0)*128 + ar] = a4.x;
        As[(ac+1)*128 + ar] = a4.y;
        As[(ac+2)*128 + ar] = a4.z;
        As[(ac+3)*128 + ar] = a4.w;

        const float* wp = Wn + (size_t)(kt + bk)*ldw + bc;
        float4 b4;
        if (bc + 4 <= nvalid) {
            b4 = *(const float4*)wp;
        } else {
            b4.x = (bc+0) < nvalid ? wp[0] : 0.f;
            b4.y = (bc+1) < nvalid ? wp[1] : 0.f;
            b4.z = (bc+2) < nvalid ? wp[2] : 0.f;
            b4.w = (bc+3) < nvalid ? wp[3] : 0.f;
        }
        *(float4*)(Bs + bk*128 + bc) = b4;
        __syncthreads();

        #pragma unroll
        for (int kk = 0; kk < 8; kk++) {
            float a[8], b[8];
            *(float4*)(a)   = *(const float4*)(As + kk*128 + ty*8);
            *(float4*)(a+4) = *(const float4*)(As + kk*128 + ty*8 + 4);
            *(float4*)(b)   = *(const float4*)(Bs + kk*128 + tx*8);
            *(float4*)(b+4) = *(const float4*)(Bs + kk*128 + tx*8 + 4);
            #pragma unroll
            for (int i = 0; i < 8; i++)
                #pragma unroll
                for (int j = 0; j < 8; j++)
                    acc[i][j] = fmaf(a[i], b[j], acc[i][j]);
        }
        __syncthreads();
    }
}

// ---------------- embedding gather + environment copy ----------------
__global__ void __launch_bounds__(256) k_embed(
    const int* __restrict__ ids, const float* __restrict__ emb,
    const float* __restrict__ env)
{
    int b = blockIdx.x, t = threadIdx.x;
    int id = ids[b];
    float* xr = g_x + (size_t)b*INSZ;
    for (int c = t; c < EE; c += 256)   xr[c]        = emb[(size_t)id*EE + c];
    for (int c = t; c < ENVD; c += 256) xr[2560 + c] = env[(size_t)b*ENVD + c];
}

// ---------------- h projections: g_hp/g_hc = h@W + b1 + b2 ----------------
__global__ void __launch_bounds__(256) k_hproj(
    const float* __restrict__ h,
    const float* __restrict__ Wp, const float* __restrict__ b1p, const float* __restrict__ b2p,
    const float* __restrict__ Wc, const float* __restrict__ b1c, const float* __restrict__ b2c)
{
    __shared__ float As[8*128], Bs[8*128];
    float acc[8][8] = {};
    int n0 = blockIdx.x * 128;
    const float* W  = blockIdx.y ? Wc  : Wp;
    const float* b1 = blockIdx.y ? b1c : b1p;
    const float* b2 = blockIdx.y ? b2c : b2p;
    float* out      = blockIdx.y ? g_hc : g_hp;   // device-code symbol ref: OK

    gemm_core(h, HH, W + n0, HH, 0, HH, 128, acc, As, Bs);

    int t = threadIdx.x, tx = t & 15, ty = t >> 4;
    #pragma unroll
    for (int i = 0; i < 8; i++) {
        int r = ty*8 + i;
        #pragma unroll
        for (int j = 0; j < 8; j++) {
            int n = n0 + tx*8 + j;
            out[(size_t)r*HH + n] = acc[i][j] + b1[n] + b2[n];
        }
    }
}

// ---------------- pure GEMM: g_U = enc @ W_e ----------------
__global__ void __launch_bounds__(256) k_attn_u(
    const float* __restrict__ enc, const float* __restrict__ W)
{
    __shared__ float As[8*128], Bs[8*128];
    float acc[8][8] = {};
    int n0 = blockIdx.x * 128;
    int m0 = blockIdx.y * 128;

    gemm_core(enc + (size_t)m0*HH, HH, W + n0, HH, 0, HH, 128, acc, As, Bs);

    int t = threadIdx.x, tx = t & 15, ty = t >> 4;
    #pragma unroll
    for (int i = 0; i < 8; i++)
        #pragma unroll
        for (int j = 0; j < 8; j++)
            g_U[(size_t)(m0 + ty*8 + i)*HH + n0 + tx*8 + j] = acc[i][j];
}

// ---------------- scores: s[m] = sum_n tanh(U[m,n] + hp[b,n]) * wa[n] ----------------
// sel=0: hp=g_hp, out=g_sP ; sel=1: hp=g_hc, out=g_sC. Selected in DEVICE code.
__global__ void __launch_bounds__(256) k_score(
    const float* __restrict__ wa, int sel)
{
    const float* hp     = sel ? g_hc : g_hp;
    float*       scores = sel ? g_sC : g_sP;
    int m = blockIdx.x;            // m = s*B + b
    int b = m & (BB-1);
    int t = threadIdx.x;
    const float* Um  = g_U + (size_t)m*HH;
    const float* hpb = hp  + (size_t)b*HH;
    float acc = 0.f;
    #pragma unroll
    for (int j = 0; j < 4; j++) {
        int n = t*4 + j;
        acc += tanh_acc(Um[n] + hpb[n]) * wa[n];
    }
    __shared__ float sm[256];
    sm[t] = acc; __syncthreads();
    for (int o = 128; o > 0; o >>= 1) {
        if (t < o) sm[t] += sm[t+o];
        __syncthreads();
    }
    if (t == 0) scores[m] = sm[0];
}

// ---------------- softmax over S per batch row ----------------
__global__ void __launch_bounds__(256) k_softmax(
    const float* __restrict__ b_a, int sel)
{
    const float* scores = sel ? g_sC : g_sP;
    float*       wout   = sel ? g_wC : g_wP;
    int b = blockIdx.x, s = threadIdx.x;   // 256 threads == S
    float sc = scores[s*BB + b] + *b_a;

    __shared__ float sm[256];
    sm[s] = sc; __syncthreads();
    for (int o = 128; o > 0; o >>= 1) {
        if (s < o) sm[s] = fmaxf(sm[s], sm[s+o]);
        __syncthreads();
    }
    float mx = sm[0]; __syncthreads();
    float e = expf(sc - mx);
    sm[s] = e; __syncthreads();
    for (int o = 128; o > 0; o >>= 1) {
        if (s < o) sm[s] += sm[s+o];
        __syncthreads();
    }
    wout[s*BB + b] = e / sm[0];
}

// ---------------- context: ctx[b,:] = sum_s w[s,b]*enc[s,b,:] -> g_x slice ----------------
// sel=0: w=g_wP, offset 512 ; sel=1: w=g_wC, offset 1536
__global__ void __launch_bounds__(256) k_context(
    const float* __restrict__ enc, int sel)
{
    const float* w  = sel ? g_wC : g_wP;
    const int   off = sel ? 1536 : 512;
    int b = blockIdx.x, t = threadIdx.x;   // t indexes float4 column 0..255
    __shared__ float ws[256];
    ws[t] = w[t*BB + b];
    __syncthreads();
    const float4* e4 = (const float4*)enc;
    float4 acc = make_float4(0.f, 0.f, 0.f, 0.f);
    #pragma unroll 8
    for (int s = 0; s < SS; s++) {
        float wv = ws[s];
        float4 v = e4[((size_t)(s*BB + b))*(HH/4) + t];
        acc.x = fmaf(wv, v.x, acc.x);
        acc.y = fmaf(wv, v.y, acc.y);
        acc.z = fmaf(wv, v.z, acc.z);
        acc.w = fmaf(wv, v.w, acc.w);
    }
    *(float4*)(g_x + (size_t)b*INSZ + off + t*4) = acc;
}

// ---------------- gates GEMM, K split into 5 chunks ----------------
__global__ void __launch_bounds__(256) k_gates_part(
    const float* __restrict__ h,
    const float* __restrict__ W_ih, const float* __restrict__ W_hh)
{
    __shared__ float As[8*128], Bs[8*128];
    float acc[8][8] = {};
    int n0 = blockIdx.x * 128;
    int ch = blockIdx.y;     // 0..3: W_ih chunks of 864, 4: W_hh
    if (ch < 4)
        gemm_core(g_x, INSZ, W_ih + n0, G4H, ch*864, (ch+1)*864, 128, acc, As, Bs);
    else
        gemm_core(h, HH, W_hh + n0, G4H, 0, HH, 128, acc, As, Bs);

    int t = threadIdx.x, tx = t & 15, ty = t >> 4;
    float* dst = g_gpart + (size_t)ch*BB*G4H;
    #pragma unroll
    for (int i = 0; i < 8; i++)
        #pragma unroll
        for (int j = 0; j < 8; j++)
            dst[(size_t)(ty*8 + i)*G4H + n0 + tx*8 + j] = acc[i][j];
}

__global__ void __launch_bounds__(256) k_gates_reduce(
    const float* __restrict__ b_ih, const float* __restrict__ b_hh)
{
    int idx = blockIdx.x*256 + threadIdx.x;     // 0..524287
    int n = idx & (G4H-1);
    float s = b_ih[n] + b_hh[n];
    #pragma unroll
    for (int p = 0; p < 5; p++) s += g_gpart[(size_t)p*BB*G4H + idx];
    g_gates[idx] = s;
}

// ---------------- LSTM cell elementwise (double transcendentals: exact) ----------------
__global__ void __launch_bounds__(256) k_lstm(
    const float* __restrict__ c0, float* __restrict__ d_out, int write_out)
{
    int idx = blockIdx.x*256 + threadIdx.x;     // 0..131071
    int b = idx >> 10, n = idx & 1023;
    const float* g = g_gates + (size_t)b*G4H;
    double gi = g[n], gf = g[1024+n], gg = g[2048+n], go = g[3072+n];
    double si = 1.0/(1.0 + exp(-gi));
    double sf = 1.0/(1.0 + exp(-gf));
    double so = 1.0/(1.0 + exp(-go));
    double c1 = sf * (double)c0[idx] + si * tanh(gg);
    double h1 = so * tanh(c1);
    g_h1[idx] = (float)h1; g_c1[idx] = (float)c1;
    if (write_out) {
        d_out[1280000 + idx] = (float)h1;
        d_out[1411072 + idx] = (float)c1;
    }
}

// ---------------- output GEMM, K split 2, N bounds ----------------
__global__ void __launch_bounds__(256) k_out_part(const float* __restrict__ Wout)
{
    __shared__ float As[8*128], Bs[8*128];
    float acc[8][8] = {};
    int n0 = blockIdx.x * 128;
    int nvalid = VV - n0; if (nvalid > 128) nvalid = 128;
    int ks = blockIdx.y;
    gemm_core(g_h1, HH, Wout + n0, VV, ks*512, (ks+1)*512, nvalid, acc, As, Bs);

    int t = threadIdx.x, tx = t & 15, ty = t >> 4;
    float* dst = g_opart + (size_t)ks*BB*VV;
    #pragma unroll
    for (int i = 0; i < 8; i++)
        #pragma unroll
        for (int j = 0; j < 8; j++) {
            int n = n0 + tx*8 + j;
            if (n < VV) dst[(size_t)(ty*8 + i)*VV + n] = acc[i][j];
        }
}

__global__ void __launch_bounds__(256) k_out_reduce(
    const float* __restrict__ b_out, float* __restrict__ out)
{
    int idx = blockIdx.x*256 + threadIdx.x;
    if (idx < BB*VV) {
        int n = idx % VV;
        out[idx] = g_opart[idx] + g_opart[(size_t)BB*VV + idx] + b_out[n];
    }
}

// ---------------- launch ----------------
extern "C" void kernel_launch(void* const* d_in, const int* in_sizes, int n_in,
                              void* d_out, int out_size)
{
    const int*   ids  = (const int*)d_in[0];
    const float* prev = (const float*)d_in[1];   // [256,128,1024]
    const float* encc = (const float*)d_in[2];   // [256,128,1024]
    const float* env  = (const float*)d_in[3];   // [128,896]
    const float* h0   = (const float*)d_in[4];   // [1,128,1024]
    const float* c0   = (const float*)d_in[5];
    const float* emb  = (const float*)d_in[6];   // [10000,512]
    const float* W_hp = (const float*)d_in[7];
    const float* b_hp = (const float*)d_in[8];
    const float* W_ep = (const float*)d_in[9];
    const float* b_ep = (const float*)d_in[10];
    const float* w_ap = (const float*)d_in[11];
    const float* b_ap = (const float*)d_in[12];
    const float* W_hc = (const float*)d_in[13];
    const float* b_hc = (const float*)d_in[14];
    const float* W_ec = (const float*)d_in[15];
    const float* b_ec = (const float*)d_in[16];
    const float* w_ac = (const float*)d_in[17];
    const float* b_ac = (const float*)d_in[18];

    // Robust to metadata ordering of (W_ih, b_ih, W_hh, b_hh) vs (W_ih, W_hh, b_ih, b_hh)
    const float* W_ih = (const float*)d_in[19];
    const float* W_hh; const float* b_ih; const float* b_hh;
    if (in_sizes[20] == 1024*4096) {  // arg order: W_ih, W_hh, b_ih, b_hh
        W_hh = (const float*)d_in[20];
        b_ih = (const float*)d_in[21];
        b_hh = (const float*)d_in[22];
    } else {                           // dict order: W_ih, b_ih, W_hh, b_hh
        b_ih = (const float*)d_in[20];
        W_hh = (const float*)d_in[21];
        b_hh = (const float*)d_in[22];
    }
    const float* W_out = (const float*)d_in[23];
    const float* b_out = (const float*)d_in[24];

    float* out = (float*)d_out;
    int write_state = (out_size >= 1542144) ? 1 : 0;

    // 1. embed + env copy into x
    k_embed<<<BB, 256>>>(ids, emb, env);
    // 2. h projections with folded biases (b_h + b_e)
    k_hproj<<<dim3(8,2), 256>>>(h0, W_hp, b_hp, b_ep, W_hc, b_hc, b_ec);
    // 3a. U = prev @ W_ep ; scores (sel=0 -> g_hp, g_sP)
    k_attn_u<<<dim3(8,256), 256>>>(prev, W_ep);
    k_score<<<MATT, 256>>>(w_ap, 0);
    // 3b. U = enc @ W_ec ; scores (sel=1 -> g_hc, g_sC)
    k_attn_u<<<dim3(8,256), 256>>>(encc, W_ec);
    k_score<<<MATT, 256>>>(w_ac, 1);
    // 4. softmax
    k_softmax<<<BB, 256>>>(b_ap, 0);
    k_softmax<<<BB, 256>>>(b_ac, 1);
    // 5. contexts -> x slices
    k_context<<<BB, 256>>>(prev, 0);
    k_context<<<BB, 256>>>(encc, 1);
    // 6. gates GEMM (K-split 5) + reduce
    k_gates_part<<<dim3(32,5), 256>>>(h0, W_ih, W_hh);
    k_gates_reduce<<<(BB*G4H)/256, 256>>>(b_ih, b_hh);
    // 7. LSTM cell
    k_lstm<<<(BB*HH)/256, 256>>>(c0, out, write_state);
    // 8. output GEMM (K-split 2) + reduce
    k_out_part<<<dim3(79,2), 256>>>(W_out);
    k_out_reduce<<<(BB*VV + 255)/256, 256>>>(b_out, out);
}

// round 8
// speedup vs baseline: 2.7942x; 2.7942x over previous
#include <cuda_runtime.h>
#include <math.h>

// Problem constants
#define BB 128
#define SS 256
#define HH 1024
#define EE 512
#define ENVD 896
#define VV 10000
#define INSZ 3456          // E + H + H + ENV
#define MATT (SS*BB)       // 32768
#define G4H 4096

// Accurate fp32 tanh immune to --use_fast_math's tanh.approx.
__device__ __forceinline__ float tanh_acc(float x) {
    float ax = fabsf(x);
    float e  = __expf(2.0f * ax);
    float t  = 1.0f - 2.0f / (e + 1.0f);
    return copysignf(t, x);
}

// fp32 -> tf32 (rna) kept in a float container (low 13 mantissa bits zero).
__device__ __forceinline__ float tf32f(float x) {
    unsigned r;
    asm("cvt.rna.tf32.f32 %0, %1;" : "=r"(r) : "f"(x));
    return __uint_as_float(r);
}

// ---------------- scratch (device globals; DEVICE-CODE-ONLY references) ----------------
__device__ float g_x[BB*INSZ];
__device__ float g_hp[BB*HH];
__device__ float g_hc[BB*HH];
__device__ float g_U[MATT*HH];
__device__ float g_sP[MATT];
__device__ float g_sC[MATT];
__device__ float g_wP[MATT];
__device__ float g_wC[MATT];
__device__ float g_gpart[5*BB*G4H];
__device__ float g_gates[BB*G4H];
__device__ float g_opart[2*BB*VV];
__device__ float g_h1[BB*HH];
__device__ float g_c1[BB*HH];

// ---------------- tf32 tensor-core GEMM core (128x128 tile, K-step 32) ----------------
// 256 threads = 8 warps; warp (mwarp = wid&3, nwarp = wid>>2) computes 32(m) x 64(n)
// via mma.sync.m16n8k8 tf32. A: row-major [128, lda]. Wn: row-major [K, ldw] offset to n0.
// As[128][36] (pad 4), Bs[32][136] (pad 8): conflict-free fragment loads.
#define AS_LD 36
#define BS_LD 136

__device__ __forceinline__ void mma_tf32(float* c, const unsigned* a, unsigned b0, unsigned b1) {
    asm volatile(
        "mma.sync.aligned.m16n8k8.row.col.f32.tf32.tf32.f32 "
        "{%0,%1,%2,%3},{%4,%5,%6,%7},{%8,%9},{%0,%1,%2,%3};"
        : "+f"(c[0]), "+f"(c[1]), "+f"(c[2]), "+f"(c[3])
        : "r"(a[0]), "r"(a[1]), "r"(a[2]), "r"(a[3]), "r"(b0), "r"(b1));
}

__device__ __forceinline__ void mma_core(
    const float* __restrict__ A, int lda,
    const float* __restrict__ Wn, int ldw,
    int k0, int k1, int nvalid,
    float (&acc)[2][8][4], float* As, float* Bs)
{
    const int t = threadIdx.x;
    const int lane = t & 31, wid = t >> 5;
    const int mwarp = wid & 3, nwarp = wid >> 2;
    const int lq = lane >> 2, lp = lane & 3;

    for (int kt = k0; kt < k1; kt += 32) {
        // A tile 128x32 -> As (tf32-rounded)
        #pragma unroll
        for (int j = 0; j < 4; j++) {
            int idx = t + 256*j;
            int row = idx >> 3, cq = (idx & 7) << 2;
            float4 v = *(const float4*)(A + (size_t)row*lda + kt + cq);
            float4 w4;
            w4.x = tf32f(v.x); w4.y = tf32f(v.y); w4.z = tf32f(v.z); w4.w = tf32f(v.w);
            *(float4*)(As + row*AS_LD + cq) = w4;
        }
        // B tile 32x128 -> Bs (tf32-rounded, N-bounded)
        #pragma unroll
        for (int j = 0; j < 4; j++) {
            int idx = t + 256*j;
            int kr = idx >> 5, nq = (idx & 31) << 2;
            float4 v;
            const float* wp = Wn + (size_t)(kt + kr)*ldw + nq;
            if (nq + 4 <= nvalid) {
                v = *(const float4*)wp;
            } else {
                v.x = (nq+0) < nvalid ? wp[0] : 0.f;
                v.y = (nq+1) < nvalid ? wp[1] : 0.f;
                v.z = (nq+2) < nvalid ? wp[2] : 0.f;
                v.w = (nq+3) < nvalid ? wp[3] : 0.f;
            }
            float4 w4;
            w4.x = tf32f(v.x); w4.y = tf32f(v.y); w4.z = tf32f(v.z); w4.w = tf32f(v.w);
            *(float4*)(Bs + kr*BS_LD + nq) = w4;
        }
        __syncthreads();

        #pragma unroll
        for (int k8 = 0; k8 < 32; k8 += 8) {
            unsigned a[2][4];
            #pragma unroll
            for (int mt = 0; mt < 2; mt++) {
                int r = mwarp*32 + mt*16 + lq;
                int c = k8 + lp;
                a[mt][0] = __float_as_uint(As[r*AS_LD + c]);
                a[mt][1] = __float_as_uint(As[(r+8)*AS_LD + c]);
                a[mt][2] = __float_as_uint(As[r*AS_LD + c + 4]);
                a[mt][3] = __float_as_uint(As[(r+8)*AS_LD + c + 4]);
            }
            #pragma unroll
            for (int nt = 0; nt < 8; nt++) {
                int n  = nwarp*64 + nt*8 + lq;
                int kb = k8 + lp;
                unsigned b0 = __float_as_uint(Bs[kb*BS_LD + n]);
                unsigned b1 = __float_as_uint(Bs[(kb+4)*BS_LD + n]);
                mma_tf32(acc[0][nt], a[0], b0, b1);
                mma_tf32(acc[1][nt], a[1], b0, b1);
            }
        }
        __syncthreads();
    }
}

// Epilogue index helpers: element (mt,nt,ci) sits at
// row = mwarp*32 + mt*16 + (lane>>2) + (ci>=2 ? 8 : 0)
// col = nwarp*64 + nt*8 + (lane&3)*2 + (ci&1)

// ---------------- embedding gather + environment copy ----------------
__global__ void __launch_bounds__(256) k_embed(
    const int* __restrict__ ids, const float* __restrict__ emb,
    const float* __restrict__ env)
{
    int b = blockIdx.x, t = threadIdx.x;
    int id = ids[b];
    float* xr = g_x + (size_t)b*INSZ;
    for (int c = t; c < EE; c += 256)   xr[c]        = emb[(size_t)id*EE + c];
    for (int c = t; c < ENVD; c += 256) xr[2560 + c] = env[(size_t)b*ENVD + c];
}

// ---------------- h projections: g_hp/g_hc = h@W + b1 + b2 ----------------
__global__ void __launch_bounds__(256, 2) k_hproj(
    const float* __restrict__ h,
    const float* __restrict__ Wp, const float* __restrict__ b1p, const float* __restrict__ b2p,
    const float* __restrict__ Wc, const float* __restrict__ b1c, const float* __restrict__ b2c)
{
    __shared__ float As[128*AS_LD], Bs[32*BS_LD];
    float acc[2][8][4] = {};
    int n0 = blockIdx.x * 128;
    const float* W  = blockIdx.y ? Wc  : Wp;
    const float* b1 = blockIdx.y ? b1c : b1p;
    const float* b2 = blockIdx.y ? b2c : b2p;
    float* out      = blockIdx.y ? g_hc : g_hp;

    mma_core(h, HH, W + n0, HH, 0, HH, 128, acc, As, Bs);

    int t = threadIdx.x, lane = t & 31, wid = t >> 5;
    int mwarp = wid & 3, nwarp = wid >> 2, lq = lane >> 2, lp = lane & 3;
    #pragma unroll
    for (int mt = 0; mt < 2; mt++)
        #pragma unroll
        for (int nt = 0; nt < 8; nt++) {
            int r  = mwarp*32 + mt*16 + lq;
            int cb = n0 + nwarp*64 + nt*8 + lp*2;
            out[(size_t)r*HH + cb]       = acc[mt][nt][0] + b1[cb]   + b2[cb];
            out[(size_t)r*HH + cb+1]     = acc[mt][nt][1] + b1[cb+1] + b2[cb+1];
            out[(size_t)(r+8)*HH + cb]   = acc[mt][nt][2] + b1[cb]   + b2[cb];
            out[(size_t)(r+8)*HH + cb+1] = acc[mt][nt][3] + b1[cb+1] + b2[cb+1];
        }
}

// ---------------- pure GEMM: g_U = enc @ W_e ----------------
__global__ void __launch_bounds__(256, 2) k_attn_u(
    const float* __restrict__ enc, const float* __restrict__ W)
{
    __shared__ float As[128*AS_LD], Bs[32*BS_LD];
    float acc[2][8][4] = {};
    int n0 = blockIdx.x * 128;
    int m0 = blockIdx.y * 128;

    mma_core(enc + (size_t)m0*HH, HH, W + n0, HH, 0, HH, 128, acc, As, Bs);

    int t = threadIdx.x, lane = t & 31, wid = t >> 5;
    int mwarp = wid & 3, nwarp = wid >> 2, lq = lane >> 2, lp = lane & 3;
    #pragma unroll
    for (int mt = 0; mt < 2; mt++)
        #pragma unroll
        for (int nt = 0; nt < 8; nt++) {
            int r  = m0 + mwarp*32 + mt*16 + lq;
            int cb = n0 + nwarp*64 + nt*8 + lp*2;
            *(float2*)(g_U + (size_t)r*HH + cb)     = make_float2(acc[mt][nt][0], acc[mt][nt][1]);
            *(float2*)(g_U + (size_t)(r+8)*HH + cb) = make_float2(acc[mt][nt][2], acc[mt][nt][3]);
        }
}

// ---------------- scores: s[m] = sum_n tanh(U[m,n] + hp[b,n]) * wa[n] ----------------
__global__ void __launch_bounds__(256) k_score(
    const float* __restrict__ wa, int sel)
{
    const float* hp     = sel ? g_hc : g_hp;
    float*       scores = sel ? g_sC : g_sP;
    int m = blockIdx.x;            // m = s*B + b
    int b = m & (BB-1);
    int t = threadIdx.x;
    const float* Um  = g_U + (size_t)m*HH;
    const float* hpb = hp  + (size_t)b*HH;
    float acc = 0.f;
    #pragma unroll
    for (int j = 0; j < 4; j++) {
        int n = t*4 + j;
        acc += tanh_acc(Um[n] + hpb[n]) * wa[n];
    }
    __shared__ float sm[256];
    sm[t] = acc; __syncthreads();
    for (int o = 128; o > 0; o >>= 1) {
        if (t < o) sm[t] += sm[t+o];
        __syncthreads();
    }
    if (t == 0) scores[m] = sm[0];
}

// ---------------- softmax over S per batch row ----------------
__global__ void __launch_bounds__(256) k_softmax(
    const float* __restrict__ b_a, int sel)
{
    const float* scores = sel ? g_sC : g_sP;
    float*       wout   = sel ? g_wC : g_wP;
    int b = blockIdx.x, s = threadIdx.x;
    float sc = scores[s*BB + b] + *b_a;

    __shared__ float sm[256];
    sm[s] = sc; __syncthreads();
    for (int o = 128; o > 0; o >>= 1) {
        if (s < o) sm[s] = fmaxf(sm[s], sm[s+o]);
        __syncthreads();
    }
    float mx = sm[0]; __syncthreads();
    float e = expf(sc - mx);
    sm[s] = e; __syncthreads();
    for (int o = 128; o > 0; o >>= 1) {
        if (s < o) sm[s] += sm[s+o];
        __syncthreads();
    }
    wout[s*BB + b] = e / sm[0];
}

// ---------------- context: ctx[b,:] = sum_s w[s,b]*enc[s,b,:] -> g_x slice ----------------
__global__ void __launch_bounds__(256) k_context(
    const float* __restrict__ enc, int sel)
{
    const float* w  = sel ? g_wC : g_wP;
    const int   off = sel ? 1536 : 512;
    int b = blockIdx.x, t = threadIdx.x;
    __shared__ float ws[256];
    ws[t] = w[t*BB + b];
    __syncthreads();
    const float4* e4 = (const float4*)enc;
    float4 acc = make_float4(0.f, 0.f, 0.f, 0.f);
    #pragma unroll 8
    for (int s = 0; s < SS; s++) {
        float wv = ws[s];
        float4 v = e4[((size_t)(s*BB + b))*(HH/4) + t];
        acc.x = fmaf(wv, v.x, acc.x);
        acc.y = fmaf(wv, v.y, acc.y);
        acc.z = fmaf(wv, v.z, acc.z);
        acc.w = fmaf(wv, v.w, acc.w);
    }
    *(float4*)(g_x + (size_t)b*INSZ + off + t*4) = acc;
}

// ---------------- gates GEMM, K split into 5 chunks ----------------
__global__ void __launch_bounds__(256, 2) k_gates_part(
    const float* __restrict__ h,
    const float* __restrict__ W_ih, const float* __restrict__ W_hh)
{
    __shared__ float As[128*AS_LD], Bs[32*BS_LD];
    float acc[2][8][4] = {};
    int n0 = blockIdx.x * 128;
    int ch = blockIdx.y;     // 0..3: W_ih chunks of 864 (27 k-steps), 4: W_hh
    if (ch < 4)
        mma_core(g_x, INSZ, W_ih + n0, G4H, ch*864, (ch+1)*864, 128, acc, As, Bs);
    else
        mma_core(h, HH, W_hh + n0, G4H, 0, HH, 128, acc, As, Bs);

    int t = threadIdx.x, lane = t & 31, wid = t >> 5;
    int mwarp = wid & 3, nwarp = wid >> 2, lq = lane >> 2, lp = lane & 3;
    float* dst = g_gpart + (size_t)ch*BB*G4H;
    #pragma unroll
    for (int mt = 0; mt < 2; mt++)
        #pragma unroll
        for (int nt = 0; nt < 8; nt++) {
            int r  = mwarp*32 + mt*16 + lq;
            int cb = n0 + nwarp*64 + nt*8 + lp*2;
            *(float2*)(dst + (size_t)r*G4H + cb)     = make_float2(acc[mt][nt][0], acc[mt][nt][1]);
            *(float2*)(dst + (size_t)(r+8)*G4H + cb) = make_float2(acc[mt][nt][2], acc[mt][nt][3]);
        }
}

__global__ void __launch_bounds__(256) k_gates_reduce(
    const float* __restrict__ b_ih, const float* __restrict__ b_hh)
{
    int idx = blockIdx.x*256 + threadIdx.x;
    int n = idx & (G4H-1);
    float s = b_ih[n] + b_hh[n];
    #pragma unroll
    for (int p = 0; p < 5; p++) s += g_gpart[(size_t)p*BB*G4H + idx];
    g_gates[idx] = s;
}

// ---------------- LSTM cell elementwise (double transcendentals: exact) ----------------
__global__ void __launch_bounds__(256) k_lstm(
    const float* __restrict__ c0, float* __restrict__ d_out, int write_out)
{
    int idx = blockIdx.x*256 + threadIdx.x;
    int b = idx >> 10, n = idx & 1023;
    const float* g = g_gates + (size_t)b*G4H;
    double gi = g[n], gf = g[1024+n], gg = g[2048+n], go = g[3072+n];
    double si = 1.0/(1.0 + exp(-gi));
    double sf = 1.0/(1.0 + exp(-gf));
    double so = 1.0/(1.0 + exp(-go));
    double c1 = sf * (double)c0[idx] + si * tanh(gg);
    double h1 = so * tanh(c1);
    g_h1[idx] = (float)h1; g_c1[idx] = (float)c1;
    if (write_out) {
        d_out[1280000 + idx] = (float)h1;
        d_out[1411072 + idx] = (float)c1;
    }
}

// ---------------- output GEMM, K split 2, N bounds ----------------
__global__ void __launch_bounds__(256, 2) k_out_part(const float* __restrict__ Wout)
{
    __shared__ float As[128*AS_LD], Bs[32*BS_LD];
    float acc[2][8][4] = {};
    int n0 = blockIdx.x * 128;
    int nvalid = VV - n0; if (nvalid > 128) nvalid = 128;
    int ks = blockIdx.y;
    mma_core(g_h1, HH, Wout + n0, VV, ks*512, (ks+1)*512, nvalid, acc, As, Bs);

    int t = threadIdx.x, lane = t & 31, wid = t >> 5;
    int mwarp = wid & 3, nwarp = wid >> 2, lq = lane >> 2, lp = lane & 3;
    float* dst = g_opart + (size_t)ks*BB*VV;
    #pragma unroll
    for (int mt = 0; mt < 2; mt++)
        #pragma unroll
        for (int nt = 0; nt < 8; nt++) {
            int r  = mwarp*32 + mt*16 + lq;
            int cb = n0 + nwarp*64 + nt*8 + lp*2;
            if (cb + 1 < VV) {   // VV even, cb even -> pair fully valid or fully out
                *(float2*)(dst + (size_t)r*VV + cb)     = make_float2(acc[mt][nt][0], acc[mt][nt][1]);
                *(float2*)(dst + (size_t)(r+8)*VV + cb) = make_float2(acc[mt][nt][2], acc[mt][nt][3]);
            }
        }
}

__global__ void __launch_bounds__(256) k_out_reduce(
    const float* __restrict__ b_out, float* __restrict__ out)
{
    int idx = blockIdx.x*256 + threadIdx.x;
    if (idx < BB*VV) {
        int n = idx % VV;
        out[idx] = g_opart[idx] + g_opart[(size_t)BB*VV + idx] + b_out[n];
    }
}

// ---------------- launch ----------------
extern "C" void kernel_launch(void* const* d_in, const int* in_sizes, int n_in,
                              void* d_out, int out_size)
{
    const int*   ids  = (const int*)d_in[0];
    const float* prev = (const float*)d_in[1];
    const float* encc = (const float*)d_in[2];
    const float* env  = (const float*)d_in[3];
    const float* h0   = (const float*)d_in[4];
    const float* c0   = (const float*)d_in[5];
    const float* emb  = (const float*)d_in[6];
    const float* W_hp = (const float*)d_in[7];
    const float* b_hp = (const float*)d_in[8];
    const float* W_ep = (const float*)d_in[9];
    const float* b_ep = (const float*)d_in[10];
    const float* w_ap = (const float*)d_in[11];
    const float* b_ap = (const float*)d_in[12];
    const float* W_hc = (const float*)d_in[13];
    const float* b_hc = (const float*)d_in[14];
    const float* W_ec = (const float*)d_in[15];
    const float* b_ec = (const float*)d_in[16];
    const float* w_ac = (const float*)d_in[17];
    const float* b_ac = (const float*)d_in[18];

    const float* W_ih = (const float*)d_in[19];
    const float* W_hh; const float* b_ih; const float* b_hh;
    if (in_sizes[20] == 1024*4096) {
        W_hh = (const float*)d_in[20];
        b_ih = (const float*)d_in[21];
        b_hh = (const float*)d_in[22];
    } else {
        b_ih = (const float*)d_in[20];
        W_hh = (const float*)d_in[21];
        b_hh = (const float*)d_in[22];
    }
    const float* W_out = (const float*)d_in[23];
    const float* b_out = (const float*)d_in[24];

    float* out = (float*)d_out;
    int write_state = (out_size >= 1542144) ? 1 : 0;

    k_embed<<<BB, 256>>>(ids, emb, env);
    k_hproj<<<dim3(8,2), 256>>>(h0, W_hp, b_hp, b_ep, W_hc, b_hc, b_ec);
    k_attn_u<<<dim3(8,256), 256>>>(prev, W_ep);
    k_score<<<MATT, 256>>>(w_ap, 0);
    k_attn_u<<<dim3(8,256), 256>>>(encc, W_ec);
    k_score<<<MATT, 256>>>(w_ac, 1);
    k_softmax<<<BB, 256>>>(b_ap, 0);
    k_softmax<<<BB, 256>>>(b_ac, 1);
    k_context<<<BB, 256>>>(prev, 0);
    k_context<<<BB, 256>>>(encc, 1);
    k_gates_part<<<dim3(32,5), 256>>>(h0, W_ih, W_hh);
    k_gates_reduce<<<(BB*G4H)/256, 256>>>(b_ih, b_hh);
    k_lstm<<<(BB*HH)/256, 256>>>(c0, out, write_state);
    k_out_part<<<dim3(79,2), 256>>>(W_out);
    k_out_reduce<<<(BB*VV + 255)/256, 256>>>(b_out, out);
}

// round 9
// speedup vs baseline: 2.9103x; 1.0415x over previous
#include <cuda_runtime.h>
#include <math.h>

// Problem constants
#define BB 128
#define SS 256
#define HH 1024
#define EE 512
#define ENVD 896
#define VV 10000
#define INSZ 3456          // E + H + H + ENV
#define MATT (SS*BB)       // 32768
#define G4H 4096

// fp32 -> tf32 (rna) kept in a float container (low 13 mantissa bits zero).
__device__ __forceinline__ float tf32f(float x) {
    unsigned r;
    asm("cvt.rna.tf32.f32 %0, %1;" : "=r"(r) : "f"(x));
    return __uint_as_float(r);
}

// ---------------- scratch (device globals; DEVICE-CODE-ONLY references) ----------------
__device__ float g_x[BB*INSZ];
__device__ float g_hp[BB*HH];
__device__ float g_hc[BB*HH];
__device__ float g_spP[8*MATT];        // score partials, [n_tile][m]
__device__ float g_spC[8*MATT];
__device__ float g_wP[MATT];
__device__ float g_wC[MATT];
__device__ float g_gpart[5*BB*G4H];
__device__ float g_gates[BB*G4H];
__device__ float g_opart[2*BB*VV];
__device__ float g_h1[BB*HH];
__device__ float g_c1[BB*HH];

// ---------------- tf32 tensor-core GEMM core (128x128 tile, K-step 32) ----------------
// 256 threads = 8 warps; warp (mwarp = wid&3, nwarp = wid>>2) computes 32(m) x 64(n)
// via mma.sync.m16n8k8 tf32. Register-prefetch pipeline: next K-tile's global
// loads are issued before the compute loop of the current tile.
#define AS_LD 36
#define BS_LD 136

__device__ __forceinline__ void mma_tf32(float* c, const unsigned* a, unsigned b0, unsigned b1) {
    asm volatile(
        "mma.sync.aligned.m16n8k8.row.col.f32.tf32.tf32.f32 "
        "{%0,%1,%2,%3},{%4,%5,%6,%7},{%8,%9},{%0,%1,%2,%3};"
        : "+f"(c[0]), "+f"(c[1]), "+f"(c[2]), "+f"(c[3])
        : "r"(a[0]), "r"(a[1]), "r"(a[2]), "r"(a[3]), "r"(b0), "r"(b1));
}

__device__ __forceinline__ void mma_core(
    const float* __restrict__ A, int lda,
    const float* __restrict__ Wn, int ldw,
    int k0, int k1, int nvalid,
    float (&acc)[2][8][4], float* As, float* Bs)
{
    const int t = threadIdx.x;
    const int lane = t & 31, wid = t >> 5;
    const int mwarp = wid & 3, nwarp = wid >> 2;
    const int lq = lane >> 2, lp = lane & 3;

    float4 ra[4], rb[4];

    // prologue: load first K-tile into registers
    #pragma unroll
    for (int j = 0; j < 4; j++) {
        int idx = t + 256*j;
        ra[j] = *(const float4*)(A + (size_t)(idx>>3)*lda + k0 + ((idx&7)<<2));
    }
    #pragma unroll
    for (int j = 0; j < 4; j++) {
        int idx = t + 256*j;
        int kr = idx >> 5, nq = (idx & 31) << 2;
        const float* wp = Wn + (size_t)(k0 + kr)*ldw + nq;
        if (nq + 4 <= nvalid) rb[j] = *(const float4*)wp;
        else {
            rb[j].x = (nq+0) < nvalid ? wp[0] : 0.f;
            rb[j].y = (nq+1) < nvalid ? wp[1] : 0.f;
            rb[j].z = (nq+2) < nvalid ? wp[2] : 0.f;
            rb[j].w = (nq+3) < nvalid ? wp[3] : 0.f;
        }
    }

    for (int kt = k0; kt < k1; kt += 32) {
        // store current registers to smem (tf32-rounded)
        #pragma unroll
        for (int j = 0; j < 4; j++) {
            int idx = t + 256*j;
            int row = idx >> 3, cq = (idx & 7) << 2;
            float4 w4;
            w4.x = tf32f(ra[j].x); w4.y = tf32f(ra[j].y);
            w4.z = tf32f(ra[j].z); w4.w = tf32f(ra[j].w);
            *(float4*)(As + row*AS_LD + cq) = w4;
        }
        #pragma unroll
        for (int j = 0; j < 4; j++) {
            int idx = t + 256*j;
            int kr = idx >> 5, nq = (idx & 31) << 2;
            float4 w4;
            w4.x = tf32f(rb[j].x); w4.y = tf32f(rb[j].y);
            w4.z = tf32f(rb[j].z); w4.w = tf32f(rb[j].w);
            *(float4*)(Bs + kr*BS_LD + nq) = w4;
        }
        __syncthreads();

        // prefetch next K-tile (overlaps with compute below)
        if (kt + 32 < k1) {
            #pragma unroll
            for (int j = 0; j < 4; j++) {
                int idx = t + 256*j;
                ra[j] = *(const float4*)(A + (size_t)(idx>>3)*lda + (kt+32) + ((idx&7)<<2));
            }
            #pragma unroll
            for (int j = 0; j < 4; j++) {
                int idx = t + 256*j;
                int kr = idx >> 5, nq = (idx & 31) << 2;
                const float* wp = Wn + (size_t)(kt + 32 + kr)*ldw + nq;
                if (nq + 4 <= nvalid) rb[j] = *(const float4*)wp;
                else {
                    rb[j].x = (nq+0) < nvalid ? wp[0] : 0.f;
                    rb[j].y = (nq+1) < nvalid ? wp[1] : 0.f;
                    rb[j].z = (nq+2) < nvalid ? wp[2] : 0.f;
                    rb[j].w = (nq+3) < nvalid ? wp[3] : 0.f;
                }
            }
        }

        #pragma unroll
        for (int k8 = 0; k8 < 32; k8 += 8) {
            unsigned a[2][4];
            #pragma unroll
            for (int mt = 0; mt < 2; mt++) {
                int r = mwarp*32 + mt*16 + lq;
                int c = k8 + lp;
                a[mt][0] = __float_as_uint(As[r*AS_LD + c]);
                a[mt][1] = __float_as_uint(As[(r+8)*AS_LD + c]);
                a[mt][2] = __float_as_uint(As[r*AS_LD + c + 4]);
                a[mt][3] = __float_as_uint(As[(r+8)*AS_LD + c + 4]);
            }
            #pragma unroll
            for (int nt = 0; nt < 8; nt++) {
                int n  = nwarp*64 + nt*8 + lq;
                int kb = k8 + lp;
                unsigned b0 = __float_as_uint(Bs[kb*BS_LD + n]);
                unsigned b1 = __float_as_uint(Bs[(kb+4)*BS_LD + n]);
                mma_tf32(acc[0][nt], a[0], b0, b1);
                mma_tf32(acc[1][nt], a[1], b0, b1);
            }
        }
        __syncthreads();
    }
}

// ---------------- embedding gather + environment copy ----------------
__global__ void __launch_bounds__(256) k_embed(
    const int* __restrict__ ids, const float* __restrict__ emb,
    const float* __restrict__ env)
{
    int b = blockIdx.x, t = threadIdx.x;
    int id = ids[b];
    float* xr = g_x + (size_t)b*INSZ;
    for (int c = t; c < EE; c += 256)   xr[c]        = emb[(size_t)id*EE + c];
    for (int c = t; c < ENVD; c += 256) xr[2560 + c] = env[(size_t)b*ENVD + c];
}

// ---------------- h projections: g_hp/g_hc = h@W + b1 + b2 ----------------
__global__ void __launch_bounds__(256) k_hproj(
    const float* __restrict__ h,
    const float* __restrict__ Wp, const float* __restrict__ b1p, const float* __restrict__ b2p,
    const float* __restrict__ Wc, const float* __restrict__ b1c, const float* __restrict__ b2c)
{
    __shared__ float As[128*AS_LD], Bs[32*BS_LD];
    float acc[2][8][4] = {};
    int n0 = blockIdx.x * 128;
    const float* W  = blockIdx.y ? Wc  : Wp;
    const float* b1 = blockIdx.y ? b1c : b1p;
    const float* b2 = blockIdx.y ? b2c : b2p;
    float* out      = blockIdx.y ? g_hc : g_hp;

    mma_core(h, HH, W + n0, HH, 0, HH, 128, acc, As, Bs);

    int t = threadIdx.x, lane = t & 31, wid = t >> 5;
    int mwarp = wid & 3, nwarp = wid >> 2, lq = lane >> 2, lp = lane & 3;
    #pragma unroll
    for (int mt = 0; mt < 2; mt++)
        #pragma unroll
        for (int nt = 0; nt < 8; nt++) {
            int r  = mwarp*32 + mt*16 + lq;
            int cb = n0 + nwarp*64 + nt*8 + lp*2;
            out[(size_t)r*HH + cb]       = acc[mt][nt][0] + b1[cb]   + b2[cb];
            out[(size_t)r*HH + cb+1]     = acc[mt][nt][1] + b1[cb+1] + b2[cb+1];
            out[(size_t)(r+8)*HH + cb]   = acc[mt][nt][2] + b1[cb]   + b2[cb];
            out[(size_t)(r+8)*HH + cb+1] = acc[mt][nt][3] + b1[cb+1] + b2[cb+1];
        }
}

// ---------------- fused attention: U-tile GEMM + tanh·wa partial-score epilogue ----------------
// Block (bx = n-tile 0..7, by = m-tile 0..255). Row r of the m-tile == batch b
// (m = s*B + b, B == 128, m0 % 128 == 0). Writes spart[bx][m0 + r].
__global__ void __launch_bounds__(256) k_attn_score(
    const float* __restrict__ enc, const float* __restrict__ W,
    const float* __restrict__ wa, int sel)
{
    __shared__ float As[128*AS_LD], Bs[32*BS_LD];
    __shared__ float red[128][8];
    float acc[2][8][4] = {};
    int n0 = blockIdx.x * 128;
    int m0 = blockIdx.y * 128;

    mma_core(enc + (size_t)m0*HH, HH, W + n0, HH, 0, HH, 128, acc, As, Bs);

    const float* hp   = sel ? g_hc : g_hp;
    float*       spart = sel ? g_spC : g_spP;

    int t = threadIdx.x, lane = t & 31, wid = t >> 5;
    int mwarp = wid & 3, nwarp = wid >> 2, lq = lane >> 2, lp = lane & 3;

    float part[2][2] = {};
    #pragma unroll
    for (int mt = 0; mt < 2; mt++) {
        int r0 = mwarp*32 + mt*16 + lq;
        const float* hp0 = hp + (size_t)r0*HH;
        const float* hp8 = hp + (size_t)(r0+8)*HH;
        #pragma unroll
        for (int nt = 0; nt < 8; nt++) {
            int cb = n0 + nwarp*64 + nt*8 + lp*2;
            float w0 = wa[cb], w1 = wa[cb+1];
            part[mt][0] += tanhf(acc[mt][nt][0] + hp0[cb])   * w0
                         + tanhf(acc[mt][nt][1] + hp0[cb+1]) * w1;
            part[mt][1] += tanhf(acc[mt][nt][2] + hp8[cb])   * w0
                         + tanhf(acc[mt][nt][3] + hp8[cb+1]) * w1;
        }
    }
    int slot = nwarp*4 + lp;
    #pragma unroll
    for (int mt = 0; mt < 2; mt++) {
        red[mwarp*32 + mt*16 + lq][slot]     = part[mt][0];
        red[mwarp*32 + mt*16 + lq + 8][slot] = part[mt][1];
    }
    __syncthreads();
    if (t < 128) {
        float s = 0.f;
        #pragma unroll
        for (int p = 0; p < 8; p++) s += red[t][p];
        spart[(size_t)blockIdx.x*MATT + m0 + t] = s;
    }
}

// ---------------- softmax over S per batch row (sums 8 n-tile partials) ----------------
__global__ void __launch_bounds__(256) k_softmax(
    const float* __restrict__ b_a, int sel)
{
    const float* spart = sel ? g_spC : g_spP;
    float*       wout  = sel ? g_wC : g_wP;
    int b = blockIdx.x, s = threadIdx.x;   // 256 threads == S
    float sc = *b_a;
    #pragma unroll
    for (int p = 0; p < 8; p++) sc += spart[(size_t)p*MATT + s*BB + b];

    __shared__ float sm[256];
    sm[s] = sc; __syncthreads();
    for (int o = 128; o > 0; o >>= 1) {
        if (s < o) sm[s] = fmaxf(sm[s], sm[s+o]);
        __syncthreads();
    }
    float mx = sm[0]; __syncthreads();
    float e = expf(sc - mx);
    sm[s] = e; __syncthreads();
    for (int o = 128; o > 0; o >>= 1) {
        if (s < o) sm[s] += sm[s+o];
        __syncthreads();
    }
    wout[s*BB + b] = e / sm[0];
}

// ---------------- context: ctx[b,:] = sum_s w[s,b]*enc[s,b,:] -> g_x slice ----------------
__global__ void __launch_bounds__(256) k_context(
    const float* __restrict__ enc, int sel)
{
    const float* w  = sel ? g_wC : g_wP;
    const int   off = sel ? 1536 : 512;
    int b = blockIdx.x, t = threadIdx.x;
    __shared__ float ws[256];
    ws[t] = w[t*BB + b];
    __syncthreads();
    const float4* e4 = (const float4*)enc;
    float4 acc = make_float4(0.f, 0.f, 0.f, 0.f);
    #pragma unroll 8
    for (int s = 0; s < SS; s++) {
        float wv = ws[s];
        float4 v = e4[((size_t)(s*BB + b))*(HH/4) + t];
        acc.x = fmaf(wv, v.x, acc.x);
        acc.y = fmaf(wv, v.y, acc.y);
        acc.z = fmaf(wv, v.z, acc.z);
        acc.w = fmaf(wv, v.w, acc.w);
    }
    *(float4*)(g_x + (size_t)b*INSZ + off + t*4) = acc;
}

// ---------------- gates GEMM, K split into 5 chunks ----------------
__global__ void __launch_bounds__(256) k_gates_part(
    const float* __restrict__ h,
    const float* __restrict__ W_ih, const float* __restrict__ W_hh)
{
    __shared__ float As[128*AS_LD], Bs[32*BS_LD];
    float acc[2][8][4] = {};
    int n0 = blockIdx.x * 128;
    int ch = blockIdx.y;     // 0..3: W_ih chunks of 864 (27 k-steps), 4: W_hh
    if (ch < 4)
        mma_core(g_x, INSZ, W_ih + n0, G4H, ch*864, (ch+1)*864, 128, acc, As, Bs);
    else
        mma_core(h, HH, W_hh + n0, G4H, 0, HH, 128, acc, As, Bs);

    int t = threadIdx.x, lane = t & 31, wid = t >> 5;
    int mwarp = wid & 3, nwarp = wid >> 2, lq = lane >> 2, lp = lane & 3;
    float* dst = g_gpart + (size_t)ch*BB*G4H;
    #pragma unroll
    for (int mt = 0; mt < 2; mt++)
        #pragma unroll
        for (int nt = 0; nt < 8; nt++) {
            int r  = mwarp*32 + mt*16 + lq;
            int cb = n0 + nwarp*64 + nt*8 + lp*2;
            *(float2*)(dst + (size_t)r*G4H + cb)     = make_float2(acc[mt][nt][0], acc[mt][nt][1]);
            *(float2*)(dst + (size_t)(r+8)*G4H + cb) = make_float2(acc[mt][nt][2], acc[mt][nt][3]);
        }
}

__global__ void __launch_bounds__(256) k_gates_reduce(
    const float* __restrict__ b_ih, const float* __restrict__ b_hh)
{
    int idx = blockIdx.x*256 + threadIdx.x;
    int n = idx & (G4H-1);
    float s = b_ih[n] + b_hh[n];
    #pragma unroll
    for (int p = 0; p < 5; p++) s += g_gpart[(size_t)p*BB*G4H + idx];
    g_gates[idx] = s;
}

// ---------------- LSTM cell elementwise (double transcendentals: exact) ----------------
__global__ void __launch_bounds__(256) k_lstm(
    const float* __restrict__ c0, float* __restrict__ d_out, int write_out)
{
    int idx = blockIdx.x*256 + threadIdx.x;
    int b = idx >> 10, n = idx & 1023;
    const float* g = g_gates + (size_t)b*G4H;
    double gi = g[n], gf = g[1024+n], gg = g[2048+n], go = g[3072+n];
    double si = 1.0/(1.0 + exp(-gi));
    double sf = 1.0/(1.0 + exp(-gf));
    double so = 1.0/(1.0 + exp(-go));
    double c1 = sf * (double)c0[idx] + si * tanh(gg);
    double h1 = so * tanh(c1);
    g_h1[idx] = (float)h1; g_c1[idx] = (float)c1;
    if (write_out) {
        d_out[1280000 + idx] = (float)h1;
        d_out[1411072 + idx] = (float)c1;
    }
}

// ---------------- output GEMM, K split 2, N bounds ----------------
__global__ void __launch_bounds__(256) k_out_part(const float* __restrict__ Wout)
{
    __shared__ float As[128*AS_LD], Bs[32*BS_LD];
    float acc[2][8][4] = {};
    int n0 = blockIdx.x * 128;
    int nvalid = VV - n0; if (nvalid > 128) nvalid = 128;
    int ks = blockIdx.y;
    mma_core(g_h1, HH, Wout + n0, VV, ks*512, (ks+1)*512, nvalid, acc, As, Bs);

    int t = threadIdx.x, lane = t & 31, wid = t >> 5;
    int mwarp = wid & 3, nwarp = wid >> 2, lq = lane >> 2, lp = lane & 3;
    float* dst = g_opart + (size_t)ks*BB*VV;
    #pragma unroll
    for (int mt = 0; mt < 2; mt++)
        #pragma unroll
        for (int nt = 0; nt < 8; nt++) {
            int r  = mwarp*32 + mt*16 + lq;
            int cb = n0 + nwarp*64 + nt*8 + lp*2;
            if (cb + 1 < VV) {
                *(float2*)(dst + (size_t)r*VV + cb)     = make_float2(acc[mt][nt][0], acc[mt][nt][1]);
                *(float2*)(dst + (size_t)(r+8)*VV + cb) = make_float2(acc[mt][nt][2], acc[mt][nt][3]);
            }
        }
}

__global__ void __launch_bounds__(256) k_out_reduce(
    const float* __restrict__ b_out, float* __restrict__ out)
{
    int idx = blockIdx.x*256 + threadIdx.x;
    if (idx < BB*VV) {
        int n = idx % VV;
        out[idx] = g_opart[idx] + g_opart[(size_t)BB*VV + idx] + b_out[n];
    }
}

// ---------------- launch ----------------
extern "C" void kernel_launch(void* const* d_in, const int* in_sizes, int n_in,
                              void* d_out, int out_size)
{
    const int*   ids  = (const int*)d_in[0];
    const float* prev = (const float*)d_in[1];
    const float* encc = (const float*)d_in[2];
    const float* env  = (const float*)d_in[3];
    const float* h0   = (const float*)d_in[4];
    const float* c0   = (const float*)d_in[5];
    const float* emb  = (const float*)d_in[6];
    const float* W_hp = (const float*)d_in[7];
    const float* b_hp = (const float*)d_in[8];
    const float* W_ep = (const float*)d_in[9];
    const float* b_ep = (const float*)d_in[10];
    const float* w_ap = (const float*)d_in[11];
    const float* b_ap = (const float*)d_in[12];
    const float* W_hc = (const float*)d_in[13];
    const float* b_hc = (const float*)d_in[14];
    const float* W_ec = (const float*)d_in[15];
    const float* b_ec = (const float*)d_in[16];
    const float* w_ac = (const float*)d_in[17];
    const float* b_ac = (const float*)d_in[18];

    const float* W_ih = (const float*)d_in[19];
    const float* W_hh; const float* b_ih; const float* b_hh;
    if (in_sizes[20] == 1024*4096) {
        W_hh = (const float*)d_in[20];
        b_ih = (const float*)d_in[21];
        b_hh = (const float*)d_in[22];
    } else {
        b_ih = (const float*)d_in[20];
        W_hh = (const float*)d_in[21];
        b_hh = (const float*)d_in[22];
    }
    const float* W_out = (const float*)d_in[23];
    const float* b_out = (const float*)d_in[24];

    float* out = (float*)d_out;
    int write_state = (out_size >= 1542144) ? 1 : 0;

    k_embed<<<BB, 256>>>(ids, emb, env);
    k_hproj<<<dim3(8,2), 256>>>(h0, W_hp, b_hp, b_ep, W_hc, b_hc, b_ec);
    k_attn_score<<<dim3(8,256), 256>>>(prev, W_ep, w_ap, 0);
    k_attn_score<<<dim3(8,256), 256>>>(encc, W_ec, w_ac, 1);
    k_softmax<<<BB, 256>>>(b_ap, 0);
    k_softmax<<<BB, 256>>>(b_ac, 1);
    k_context<<<BB, 256>>>(prev, 0);
    k_context<<<BB, 256>>>(encc, 1);
    k_gates_part<<<dim3(32,5), 256>>>(h0, W_ih, W_hh);
    k_gates_reduce<<<(BB*G4H)/256, 256>>>(b_ih, b_hh);
    k_lstm<<<(BB*HH)/256, 256>>>(c0, out, write_state);
    k_out_part<<<dim3(79,2), 256>>>(W_out);
    k_out_reduce<<<(BB*VV + 255)/256, 256>>>(b_out, out);
}

// round 10
// speedup vs baseline: 3.2239x; 1.1078x over previous
#include <cuda_runtime.h>
#include <math.h>

// Problem constants
#define BB 128
#define SS 256
#define HH 1024
#define EE 512
#define ENVD 896
#define VV 10000
#define INSZ 3456          // E + H + H + ENV
#define MATT (SS*BB)       // 32768
#define G4H 4096

// fp32 -> tf32 (rna) kept in a float container (low 13 mantissa bits zero).
__device__ __forceinline__ float tf32f(float x) {
    unsigned r;
    asm("cvt.rna.tf32.f32 %0, %1;" : "=r"(r) : "f"(x));
    return __uint_as_float(r);
}

// ---------------- scratch (device globals; DEVICE-CODE-ONLY references) ----------------
__device__ float g_x[BB*INSZ];
__device__ float g_hp[BB*HH];
__device__ float g_hc[BB*HH];
__device__ float g_spP[8*MATT];        // score partials, [n_tile][m]
__device__ float g_spC[8*MATT];
__device__ float g_wP[MATT];
__device__ float g_wC[MATT];
__device__ float g_gpart[5*BB*G4H];
__device__ float g_gates[BB*G4H];
__device__ float g_opart[2*BB*VV];
__device__ float g_h1[BB*HH];
__device__ float g_c1[BB*HH];

// ---------------- tf32 tensor-core GEMM core, 2-stage smem pipeline ----------------
// 256 threads = 8 warps; warp (mwarp = wid&3, nwarp = wid>>2) computes 32(m) x 64(n)
// via mma.sync.m16n8k8 tf32. Double-buffered smem: one __syncthreads per K-tile;
// STS of tile i+1 and LDG of tile i+2 overlap the MMA stream of tile i.
#define AS_LD 36
#define BS_LD 136
#define STAGE_F (128*AS_LD + 32*BS_LD)      // 8960 floats per stage
#define SMEM_BYTES (2*STAGE_F*4)            // 71680 bytes

__device__ __forceinline__ void mma_tf32(float* c, const unsigned* a, unsigned b0, unsigned b1) {
    asm volatile(
        "mma.sync.aligned.m16n8k8.row.col.f32.tf32.tf32.f32 "
        "{%0,%1,%2,%3},{%4,%5,%6,%7},{%8,%9},{%0,%1,%2,%3};"
        : "+f"(c[0]), "+f"(c[1]), "+f"(c[2]), "+f"(c[3])
        : "r"(a[0]), "r"(a[1]), "r"(a[2]), "r"(a[3]), "r"(b0), "r"(b1));
}

__device__ __forceinline__ void ldg_tile(
    const float* __restrict__ A, int lda,
    const float* __restrict__ Wn, int ldw,
    int kt, int nvalid, int t, float4 (&ra)[4], float4 (&rb)[4])
{
    #pragma unroll
    for (int j = 0; j < 4; j++) {
        int idx = t + 256*j;
        ra[j] = *(const float4*)(A + (size_t)(idx>>3)*lda + kt + ((idx&7)<<2));
    }
    #pragma unroll
    for (int j = 0; j < 4; j++) {
        int idx = t + 256*j;
        int kr = idx >> 5, nq = (idx & 31) << 2;
        const float* wp = Wn + (size_t)(kt + kr)*ldw + nq;
        if (nq + 4 <= nvalid) rb[j] = *(const float4*)wp;
        else {
            rb[j].x = (nq+0) < nvalid ? wp[0] : 0.f;
            rb[j].y = (nq+1) < nvalid ? wp[1] : 0.f;
            rb[j].z = (nq+2) < nvalid ? wp[2] : 0.f;
            rb[j].w = (nq+3) < nvalid ? wp[3] : 0.f;
        }
    }
}

__device__ __forceinline__ void sts_tile(
    float* __restrict__ As, float* __restrict__ Bs, int t,
    const float4 (&ra)[4], const float4 (&rb)[4])
{
    #pragma unroll
    for (int j = 0; j < 4; j++) {
        int idx = t + 256*j;
        float4 w4;
        w4.x = tf32f(ra[j].x); w4.y = tf32f(ra[j].y);
        w4.z = tf32f(ra[j].z); w4.w = tf32f(ra[j].w);
        *(float4*)(As + (idx>>3)*AS_LD + ((idx&7)<<2)) = w4;
    }
    #pragma unroll
    for (int j = 0; j < 4; j++) {
        int idx = t + 256*j;
        float4 w4;
        w4.x = tf32f(rb[j].x); w4.y = tf32f(rb[j].y);
        w4.z = tf32f(rb[j].z); w4.w = tf32f(rb[j].w);
        *(float4*)(Bs + (idx>>5)*BS_LD + ((idx&31)<<2)) = w4;
    }
}

__device__ __forceinline__ void compute_tile(
    const float* __restrict__ As, const float* __restrict__ Bs,
    float (&acc)[2][8][4], int mwarp, int nwarp, int lq, int lp)
{
    #pragma unroll
    for (int k8 = 0; k8 < 32; k8 += 8) {
        unsigned a[2][4];
        #pragma unroll
        for (int mt = 0; mt < 2; mt++) {
            int r = mwarp*32 + mt*16 + lq;
            int c = k8 + lp;
            a[mt][0] = __float_as_uint(As[r*AS_LD + c]);
            a[mt][1] = __float_as_uint(As[(r+8)*AS_LD + c]);
            a[mt][2] = __float_as_uint(As[r*AS_LD + c + 4]);
            a[mt][3] = __float_as_uint(As[(r+8)*AS_LD + c + 4]);
        }
        #pragma unroll
        for (int nt = 0; nt < 8; nt++) {
            int n  = nwarp*64 + nt*8 + lq;
            int kb = k8 + lp;
            unsigned b0 = __float_as_uint(Bs[kb*BS_LD + n]);
            unsigned b1 = __float_as_uint(Bs[(kb+4)*BS_LD + n]);
            mma_tf32(acc[0][nt], a[0], b0, b1);
            mma_tf32(acc[1][nt], a[1], b0, b1);
        }
    }
}

__device__ __forceinline__ void mma_core_pipe(
    const float* __restrict__ A, int lda,
    const float* __restrict__ Wn, int ldw,
    int k0, int k1, int nvalid,
    float (&acc)[2][8][4], float* smem)
{
    const int t = threadIdx.x;
    const int lane = t & 31, wid = t >> 5;
    const int mwarp = wid & 3, nwarp = wid >> 2;
    const int lq = lane >> 2, lp = lane & 3;

    float* As0 = smem;
    float* Bs0 = smem + 128*AS_LD;
    float* As1 = smem + STAGE_F;
    float* Bs1 = smem + STAGE_F + 128*AS_LD;

    const int nsteps = (k1 - k0) >> 5;
    float4 ra[4], rb[4];

    // prologue: tile 0 -> smem buf0; tile 1 -> regs
    ldg_tile(A, lda, Wn, ldw, k0, nvalid, t, ra, rb);
    sts_tile(As0, Bs0, t, ra, rb);
    if (nsteps > 1) ldg_tile(A, lda, Wn, ldw, k0 + 32, nvalid, t, ra, rb);
    __syncthreads();

    for (int i = 0; i < nsteps; i++) {
        // write tile i+1 into the other buffer (its last readers finished
        // at the sync ending iteration i-1), then prefetch tile i+2.
        if (i + 1 < nsteps) {
            if ((i + 1) & 1) sts_tile(As1, Bs1, t, ra, rb);
            else             sts_tile(As0, Bs0, t, ra, rb);
            if (i + 2 < nsteps)
                ldg_tile(A, lda, Wn, ldw, k0 + 32*(i+2), nvalid, t, ra, rb);
        }
        if (i & 1) compute_tile(As1, Bs1, acc, mwarp, nwarp, lq, lp);
        else       compute_tile(As0, Bs0, acc, mwarp, nwarp, lq, lp);
        __syncthreads();
    }
}

// ---------------- embedding gather + environment copy ----------------
__global__ void __launch_bounds__(256) k_embed(
    const int* __restrict__ ids, const float* __restrict__ emb,
    const float* __restrict__ env)
{
    int b = blockIdx.x, t = threadIdx.x;
    int id = ids[b];
    float* xr = g_x + (size_t)b*INSZ;
    for (int c = t; c < EE; c += 256)   xr[c]        = emb[(size_t)id*EE + c];
    for (int c = t; c < ENVD; c += 256) xr[2560 + c] = env[(size_t)b*ENVD + c];
}

// ---------------- h projections: g_hp/g_hc = h@W + b1 + b2 ----------------
__global__ void __launch_bounds__(256) k_hproj(
    const float* __restrict__ h,
    const float* __restrict__ Wp, const float* __restrict__ b1p, const float* __restrict__ b2p,
    const float* __restrict__ Wc, const float* __restrict__ b1c, const float* __restrict__ b2c)
{
    extern __shared__ float smem[];
    float acc[2][8][4] = {};
    int n0 = blockIdx.x * 128;
    const float* W  = blockIdx.y ? Wc  : Wp;
    const float* b1 = blockIdx.y ? b1c : b1p;
    const float* b2 = blockIdx.y ? b2c : b2p;
    float* out      = blockIdx.y ? g_hc : g_hp;

    mma_core_pipe(h, HH, W + n0, HH, 0, HH, 128, acc, smem);

    int t = threadIdx.x, lane = t & 31, wid = t >> 5;
    int mwarp = wid & 3, nwarp = wid >> 2, lq = lane >> 2, lp = lane & 3;
    #pragma unroll
    for (int mt = 0; mt < 2; mt++)
        #pragma unroll
        for (int nt = 0; nt < 8; nt++) {
            int r  = mwarp*32 + mt*16 + lq;
            int cb = n0 + nwarp*64 + nt*8 + lp*2;
            out[(size_t)r*HH + cb]       = acc[mt][nt][0] + b1[cb]   + b2[cb];
            out[(size_t)r*HH + cb+1]     = acc[mt][nt][1] + b1[cb+1] + b2[cb+1];
            out[(size_t)(r+8)*HH + cb]   = acc[mt][nt][2] + b1[cb]   + b2[cb];
            out[(size_t)(r+8)*HH + cb+1] = acc[mt][nt][3] + b1[cb+1] + b2[cb+1];
        }
}

// ---------------- fused attention: U-tile GEMM + tanh·wa partial-score epilogue ----------------
__global__ void __launch_bounds__(256) k_attn_score(
    const float* __restrict__ enc, const float* __restrict__ W,
    const float* __restrict__ wa, int sel)
{
    extern __shared__ float smem[];
    __shared__ float red[128][8];
    float acc[2][8][4] = {};
    int n0 = blockIdx.x * 128;
    int m0 = blockIdx.y * 128;

    mma_core_pipe(enc + (size_t)m0*HH, HH, W + n0, HH, 0, HH, 128, acc, smem);

    const float* hp    = sel ? g_hc : g_hp;
    float*       spart = sel ? g_spC : g_spP;

    int t = threadIdx.x, lane = t & 31, wid = t >> 5;
    int mwarp = wid & 3, nwarp = wid >> 2, lq = lane >> 2, lp = lane & 3;

    float part[2][2] = {};
    #pragma unroll
    for (int mt = 0; mt < 2; mt++) {
        int r0 = mwarp*32 + mt*16 + lq;
        const float* hp0 = hp + (size_t)r0*HH;
        const float* hp8 = hp + (size_t)(r0+8)*HH;
        #pragma unroll
        for (int nt = 0; nt < 8; nt++) {
            int cb = n0 + nwarp*64 + nt*8 + lp*2;
            float w0 = wa[cb], w1 = wa[cb+1];
            part[mt][0] += tanhf(acc[mt][nt][0] + hp0[cb])   * w0
                         + tanhf(acc[mt][nt][1] + hp0[cb+1]) * w1;
            part[mt][1] += tanhf(acc[mt][nt][2] + hp8[cb])   * w0
                         + tanhf(acc[mt][nt][3] + hp8[cb+1]) * w1;
        }
    }
    int slot = nwarp*4 + lp;
    #pragma unroll
    for (int mt = 0; mt < 2; mt++) {
        red[mwarp*32 + mt*16 + lq][slot]     = part[mt][0];
        red[mwarp*32 + mt*16 + lq + 8][slot] = part[mt][1];
    }
    __syncthreads();
    if (t < 128) {
        float s = 0.f;
        #pragma unroll
        for (int p = 0; p < 8; p++) s += red[t][p];
        spart[(size_t)blockIdx.x*MATT + m0 + t] = s;
    }
}

// ---------------- softmax over S per batch row (sums 8 n-tile partials) ----------------
__global__ void __launch_bounds__(256) k_softmax(
    const float* __restrict__ b_a, int sel)
{
    const float* spart = sel ? g_spC : g_spP;
    float*       wout  = sel ? g_wC : g_wP;
    int b = blockIdx.x, s = threadIdx.x;   // 256 threads == S
    float sc = *b_a;
    #pragma unroll
    for (int p = 0; p < 8; p++) sc += spart[(size_t)p*MATT + s*BB + b];

    __shared__ float sm[256];
    sm[s] = sc; __syncthreads();
    for (int o = 128; o > 0; o >>= 1) {
        if (s < o) sm[s] = fmaxf(sm[s], sm[s+o]);
        __syncthreads();
    }
    float mx = sm[0]; __syncthreads();
    float e = expf(sc - mx);
    sm[s] = e; __syncthreads();
    for (int o = 128; o > 0; o >>= 1) {
        if (s < o) sm[s] += sm[s+o];
        __syncthreads();
    }
    wout[s*BB + b] = e / sm[0];
}

// ---------------- context: ctx[b,:] = sum_s w[s,b]*enc[s,b,:] -> g_x slice ----------------
__global__ void __launch_bounds__(256) k_context(
    const float* __restrict__ enc, int sel)
{
    const float* w  = sel ? g_wC : g_wP;
    const int   off = sel ? 1536 : 512;
    int b = blockIdx.x, t = threadIdx.x;
    __shared__ float ws[256];
    ws[t] = w[t*BB + b];
    __syncthreads();
    const float4* e4 = (const float4*)enc;
    float4 acc = make_float4(0.f, 0.f, 0.f, 0.f);
    #pragma unroll 8
    for (int s = 0; s < SS; s++) {
        float wv = ws[s];
        float4 v = e4[((size_t)(s*BB + b))*(HH/4) + t];
        acc.x = fmaf(wv, v.x, acc.x);
        acc.y = fmaf(wv, v.y, acc.y);
        acc.z = fmaf(wv, v.z, acc.z);
        acc.w = fmaf(wv, v.w, acc.w);
    }
    *(float4*)(g_x + (size_t)b*INSZ + off + t*4) = acc;
}

// ---------------- gates GEMM, K split into 5 chunks ----------------
__global__ void __launch_bounds__(256) k_gates_part(
    const float* __restrict__ h,
    const float* __restrict__ W_ih, const float* __restrict__ W_hh)
{
    extern __shared__ float smem[];
    float acc[2][8][4] = {};
    int n0 = blockIdx.x * 128;
    int ch = blockIdx.y;     // 0..3: W_ih chunks of 864 (27 k-steps), 4: W_hh
    if (ch < 4)
        mma_core_pipe(g_x, INSZ, W_ih + n0, G4H, ch*864, (ch+1)*864, 128, acc, smem);
    else
        mma_core_pipe(h, HH, W_hh + n0, G4H, 0, HH, 128, acc, smem);

    int t = threadIdx.x, lane = t & 31, wid = t >> 5;
    int mwarp = wid & 3, nwarp = wid >> 2, lq = lane >> 2, lp = lane & 3;
    float* dst = g_gpart + (size_t)ch*BB*G4H;
    #pragma unroll
    for (int mt = 0; mt < 2; mt++)
        #pragma unroll
        for (int nt = 0; nt < 8; nt++) {
            int r  = mwarp*32 + mt*16 + lq;
            int cb = n0 + nwarp*64 + nt*8 + lp*2;
            *(float2*)(dst + (size_t)r*G4H + cb)     = make_float2(acc[mt][nt][0], acc[mt][nt][1]);
            *(float2*)(dst + (size_t)(r+8)*G4H + cb) = make_float2(acc[mt][nt][2], acc[mt][nt][3]);
        }
}

__global__ void __launch_bounds__(256) k_gates_reduce(
    const float* __restrict__ b_ih, const float* __restrict__ b_hh)
{
    int idx = blockIdx.x*256 + threadIdx.x;
    int n = idx & (G4H-1);
    float s = b_ih[n] + b_hh[n];
    #pragma unroll
    for (int p = 0; p < 5; p++) s += g_gpart[(size_t)p*BB*G4H + idx];
    g_gates[idx] = s;
}

// ---------------- LSTM cell elementwise (double transcendentals: exact) ----------------
__global__ void __launch_bounds__(256) k_lstm(
    const float* __restrict__ c0, float* __restrict__ d_out, int write_out)
{
    int idx = blockIdx.x*256 + threadIdx.x;
    int b = idx >> 10, n = idx & 1023;
    const float* g = g_gates + (size_t)b*G4H;
    double gi = g[n], gf = g[1024+n], gg = g[2048+n], go = g[3072+n];
    double si = 1.0/(1.0 + exp(-gi));
    double sf = 1.0/(1.0 + exp(-gf));
    double so = 1.0/(1.0 + exp(-go));
    double c1 = sf * (double)c0[idx] + si * tanh(gg);
    double h1 = so * tanh(c1);
    g_h1[idx] = (float)h1; g_c1[idx] = (float)c1;
    if (write_out) {
        d_out[1280000 + idx] = (float)h1;
        d_out[1411072 + idx] = (float)c1;
    }
}

// ---------------- output GEMM, K split 2, N bounds ----------------
__global__ void __launch_bounds__(256) k_out_part(const float* __restrict__ Wout)
{
    extern __shared__ float smem[];
    float acc[2][8][4] = {};
    int n0 = blockIdx.x * 128;
    int nvalid = VV - n0; if (nvalid > 128) nvalid = 128;
    int ks = blockIdx.y;
    mma_core_pipe(g_h1, HH, Wout + n0, VV, ks*512, (ks+1)*512, nvalid, acc, smem);

    int t = threadIdx.x, lane = t & 31, wid = t >> 5;
    int mwarp = wid & 3, nwarp = wid >> 2, lq = lane >> 2, lp = lane & 3;
    float* dst = g_opart + (size_t)ks*BB*VV;
    #pragma unroll
    for (int mt = 0; mt < 2; mt++)
        #pragma unroll
        for (int nt = 0; nt < 8; nt++) {
            int r  = mwarp*32 + mt*16 + lq;
            int cb = n0 + nwarp*64 + nt*8 + lp*2;
            if (cb + 1 < VV) {
                *(float2*)(dst + (size_t)r*VV + cb)     = make_float2(acc[mt][nt][0], acc[mt][nt][1]);
                *(float2*)(dst + (size_t)(r+8)*VV + cb) = make_float2(acc[mt][nt][2], acc[mt][nt][3]);
            }
        }
}

__global__ void __launch_bounds__(256) k_out_reduce(
    const float* __restrict__ b_out, float* __restrict__ out)
{
    int idx = blockIdx.x*256 + threadIdx.x;
    if (idx < BB*VV) {
        int n = idx % VV;
        out[idx] = g_opart[idx] + g_opart[(size_t)BB*VV + idx] + b_out[n];
    }
}

// ---------------- launch ----------------
extern "C" void kernel_launch(void* const* d_in, const int* in_sizes, int n_in,
                              void* d_out, int out_size)
{
    const int*   ids  = (const int*)d_in[0];
    const float* prev = (const float*)d_in[1];
    const float* encc = (const float*)d_in[2];
    const float* env  = (const float*)d_in[3];
    const float* h0   = (const float*)d_in[4];
    const float* c0   = (const float*)d_in[5];
    const float* emb  = (const float*)d_in[6];
    const float* W_hp = (const float*)d_in[7];
    const float* b_hp = (const float*)d_in[8];
    const float* W_ep = (const float*)d_in[9];
    const float* b_ep = (const float*)d_in[10];
    const float* w_ap = (const float*)d_in[11];
    const float* b_ap = (const float*)d_in[12];
    const float* W_hc = (const float*)d_in[13];
    const float* b_hc = (const float*)d_in[14];
    const float* W_ec = (const float*)d_in[15];
    const float* b_ec = (const float*)d_in[16];
    const float* w_ac = (const float*)d_in[17];
    const float* b_ac = (const float*)d_in[18];

    const float* W_ih = (const float*)d_in[19];
    const float* W_hh; const float* b_ih; const float* b_hh;
    if (in_sizes[20] == 1024*4096) {
        W_hh = (const float*)d_in[20];
        b_ih = (const float*)d_in[21];
        b_hh = (const float*)d_in[22];
    } else {
        b_ih = (const float*)d_in[20];
        W_hh = (const float*)d_in[21];
        b_hh = (const float*)d_in[22];
    }
    const float* W_out = (const float*)d_in[23];
    const float* b_out = (const float*)d_in[24];

    float* out = (float*)d_out;
    int write_state = (out_size >= 1542144) ? 1 : 0;

    // Raise dynamic-smem limit (host-side attribute; idempotent, capture-safe).
    cudaFuncSetAttribute(k_hproj,      cudaFuncAttributeMaxDynamicSharedMemorySize, SMEM_BYTES);
    cudaFuncSetAttribute(k_attn_score, cudaFuncAttributeMaxDynamicSharedMemorySize, SMEM_BYTES);
    cudaFuncSetAttribute(k_gates_part, cudaFuncAttributeMaxDynamicSharedMemorySize, SMEM_BYTES);
    cudaFuncSetAttribute(k_out_part,   cudaFuncAttributeMaxDynamicSharedMemorySize, SMEM_BYTES);

    k_embed<<<BB, 256>>>(ids, emb, env);
    k_hproj<<<dim3(8,2), 256, SMEM_BYTES>>>(h0, W_hp, b_hp, b_ep, W_hc, b_hc, b_ec);
    k_attn_score<<<dim3(8,256), 256, SMEM_BYTES>>>(prev, W_ep, w_ap, 0);
    k_attn_score<<<dim3(8,256), 256, SMEM_BYTES>>>(encc, W_ec, w_ac, 1);
    k_softmax<<<BB, 256>>>(b_ap, 0);
    k_softmax<<<BB, 256>>>(b_ac, 1);
    k_context<<<BB, 256>>>(prev, 0);
    k_context<<<BB, 256>>>(encc, 1);
    k_gates_part<<<dim3(32,5), 256, SMEM_BYTES>>>(h0, W_ih, W_hh);
    k_gates_reduce<<<(BB*G4H)/256, 256>>>(b_ih, b_hh);
    k_lstm<<<(BB*HH)/256, 256>>>(c0, out, write_state);
    k_out_part<<<dim3(79,2), 256, SMEM_BYTES>>>(W_out);
    k_out_reduce<<<(BB*VV + 255)/256, 256>>>(b_out, out);
}